// round 7
// baseline (speedup 1.0000x reference)
#include <cuda_runtime.h>
#include <cuda_bf16.h>
#include <math.h>
#include <stdint.h>

// ---------------- problem constants ----------------
#define BATCH 8
#define TSTEPS 16
#define CIN0 192
#define HC0 64
#define HC1 32
#define HC2 64
#define IMG_H 28
#define IMG_W 28
#define HW 784

// ---------------- device scratch (no allocs allowed) ----------------
__device__ float g_gx0[(size_t)BATCH * TSTEPS * 4 * HC0 * HW];

// double-buffered h (a/b) + single c per layer
#define SZ0 (BATCH * HC0 * HW)
#define SZ1 (BATCH * HC1 * HW)
#define SZ2 (BATCH * HC2 * HW)
#define OFF_H0A 0
#define OFF_H0B (OFF_H0A + SZ0)
#define OFF_C0  (OFF_H0B + SZ0)
#define OFF_H1A (OFF_C0  + SZ0)
#define OFF_H1B (OFF_H1A + SZ1)
#define OFF_C1  (OFF_H1B + SZ1)
#define OFF_H2A (OFF_C1  + SZ1)
#define OFF_H2B (OFF_H2A + SZ2)
#define OFF_C2  (OFF_H2B + SZ2)
#define NSTATE  (OFF_C2  + SZ2)
__device__ float g_state[NSTATE];

// pre-transposed tf32 weight buffers, layout [y][chunk][tap][m(32)][ci(8)]
#define WPC 2304
#define WOFF_GX0 0
#define WSZ_GX0 (8 * 24 * WPC)
#define WOFF_L0 (WOFF_GX0 + WSZ_GX0)
#define WSZ_L0  (8 * 8 * WPC)
#define WOFF_L1 (WOFF_L0 + WSZ_L0)
#define WSZ_L1  (4 * 12 * WPC)
#define WOFF_L2 (WOFF_L1 + WSZ_L1)
#define WSZ_L2  (8 * 12 * WPC)
#define WTOTAL  (WOFF_L2 + WSZ_L2)
__device__ uint32_t g_wt[WTOTAL];

__global__ void init_zero_kernel(float* p, int n) {
    int i = blockIdx.x * blockDim.x + threadIdx.x;
    if (i < n) p[i] = 0.f;
}

// ---------------- tf32 helpers ----------------
__device__ __forceinline__ uint32_t f2tf32(float f) {
    uint32_t u;
    asm("cvt.rna.tf32.f32 %0, %1;" : "=r"(u) : "f"(f));
    return u;
}

__device__ __forceinline__ void mma_tf32(float c[4],
                                         uint32_t a0, uint32_t a1, uint32_t a2, uint32_t a3,
                                         uint32_t b0, uint32_t b1) {
    asm volatile(
        "mma.sync.aligned.m16n8k8.row.col.f32.tf32.tf32.f32 "
        "{%0,%1,%2,%3}, {%4,%5,%6,%7}, {%8,%9}, {%0,%1,%2,%3};"
        : "+f"(c[0]), "+f"(c[1]), "+f"(c[2]), "+f"(c[3])
        : "r"(a0), "r"(a1), "r"(a2), "r"(a3), "r"(b0), "r"(b1));
}

__device__ __forceinline__ float sigmoidf_(float x) {
    return 1.0f / (1.0f + __expf(-x));
}

// ---------------- weight prep: transpose + tf32 ----------------
__global__ void prep_weights(const float* __restrict__ WA, int cinA,
                             const float* __restrict__ WB, int cinB,
                             int HC, int chunks, uint32_t* __restrict__ dst, int total)
{
    int idx = blockIdx.x * blockDim.x + threadIdx.x;
    if (idx >= total) return;
    int ci  = idx & 7;
    int m   = (idx >> 3) & 31;
    int tap = (idx >> 8) % 9;
    int chy = idx / WPC;
    int ch  = chy % chunks;
    int y   = chy / chunks;
    int oc  = (m >> 3) * HC + y * 8 + (m & 7);
    int cg  = ch * 8 + ci;
    float w;
    if (cg < cinA) w = WA[((size_t)oc * cinA + cg) * 9 + tap];
    else           w = WB[((size_t)oc * cinB + (cg - cinA)) * 9 + tap];
    dst[idx] = f2tf32(w);
}

// ---------------- conv 3x3 + fused LSTM body (device function) ----------------
#define SIN_STR 200

struct SmemU {
    union {
        struct {
            uint32_t in[2][8 * SIN_STR];
            uint32_t w[2][WPC];
        } mm;
        float gates[4 * 8 * 112];
    };
};

__device__ __forceinline__ void conv_cell_body(
    SmemU& sm,
    int n, int yb, int rowbase,
    const float* __restrict__ inA, int cinA, size_t inAStride,
    const float* __restrict__ inB, int cinB,
    const uint32_t* __restrict__ wt,
    const float* __restrict__ bias,
    const float* __restrict__ pre, size_t preStride,
    int HC,
    float* __restrict__ out, size_t outStride,   // plain path (hout == nullptr)
    const float* __restrict__ Wp,
    float* __restrict__ hout, float* __restrict__ c,
    float* __restrict__ yout, int t)
{
    const int hcb = yb * 8;

    const int tid    = threadIdx.x;
    const int lane   = tid & 31;
    const int wid    = tid >> 5;
    const int warp_m = wid & 1;
    const int warp_n = wid >> 1;
    const int g      = lane >> 2;
    const int ctg    = lane & 3;

    const int chunks = (cinA + cinB) >> 3;

    int off[7];
#pragma unroll
    for (int s = 0; s < 7; ++s) {
        int nl = warp_n * 56 + s * 8 + g;
        int r = nl / 28;
        off[s] = r * 30 + (nl - r * 28);
    }

    float acc[7][4];
#pragma unroll
    for (int s = 0; s < 7; ++s)
#pragma unroll
        for (int j = 0; j < 4; ++j) acc[s][j] = 0.f;

    float rin[12];
    uint4 rw4[5];

    auto load_chunk = [&](int ch) {
        const int cstart = ch * 8;
        const float* src = (cstart < cinA)
            ? inA + (size_t)n * inAStride + (size_t)cstart * HW
            : inB + ((size_t)n * cinB + (cstart - cinA)) * HW;
#pragma unroll
        for (int k = 0; k < 12; ++k) {
            int idx = tid + k * 128;
            float v = 0.f;
            if (idx < 1440) {
                int ci  = idx / 180;
                int rem = idx - ci * 180;
                int pr  = rem / 30;
                int gr  = rowbase + pr - 1;
                int gc  = (rem - pr * 30) - 1;
                if (gr >= 0 && gr < IMG_H && gc >= 0 && gc < IMG_W)
                    v = src[(size_t)ci * HW + gr * IMG_W + gc];
            }
            rin[k] = v;
        }
        const uint4* wsrc = (const uint4*)(wt + ((size_t)yb * chunks + ch) * WPC);
#pragma unroll
        for (int k = 0; k < 5; ++k) {
            int i4 = tid + k * 128;
            if (i4 < 576) rw4[k] = wsrc[i4];
        }
    };

    load_chunk(0);

    for (int ch = 0; ch < chunks; ++ch) {
        const int st = ch & 1;
#pragma unroll
        for (int k = 0; k < 12; ++k) {
            int idx = tid + k * 128;
            if (idx < 1440) {
                int ci  = idx / 180;
                int rem = idx - ci * 180;
                sm.mm.in[st][ci * SIN_STR + rem] = f2tf32(rin[k]);
            }
        }
#pragma unroll
        for (int k = 0; k < 5; ++k) {
            int i4 = tid + k * 128;
            if (i4 < 576) ((uint4*)sm.mm.w[st])[i4] = rw4[k];
        }
        __syncthreads();

        if (ch + 1 < chunks) load_chunk(ch + 1);

        const uint32_t* win = sm.mm.in[st];
        const uint32_t* ww  = sm.mm.w[st];
#pragma unroll
        for (int kr = 0; kr < 3; ++kr) {
#pragma unroll
            for (int kc = 0; kc < 3; ++kc) {
                const int tap = kr * 3 + kc;
                const uint32_t* wp = ww + tap * 256 + (warp_m * 16 + g) * 8 + ctg;
                uint32_t a0 = wp[0];
                uint32_t a1 = wp[64];
                uint32_t a2 = wp[4];
                uint32_t a3 = wp[68];
                const int bbase = ctg * SIN_STR + kr * 30 + kc;
#pragma unroll
                for (int s = 0; s < 7; ++s) {
                    uint32_t b0 = win[bbase + off[s]];
                    uint32_t b1 = win[bbase + off[s] + 4 * SIN_STR];
                    mma_tf32(acc[s], a0, a1, a2, a3, b0, b1);
                }
            }
        }
    }

    // ---- epilogue ----
    const int m0  = warp_m * 16 + g;
    const int oc0 = (m0 >> 3) * HC + hcb + (m0 & 7);
    const int m1  = m0 + 8;
    const int oc1 = (m1 >> 3) * HC + hcb + (m1 & 7);
    float bv0 = 0.f, bv1 = 0.f;
    if (bias) { bv0 = bias[oc0]; bv1 = bias[oc1]; }

    if (hout == nullptr) {
#pragma unroll
        for (int s = 0; s < 7; ++s) {
#pragma unroll
            for (int j = 0; j < 2; ++j) {
                int nl = warp_n * 56 + s * 8 + 2 * ctg + j;
                int r = nl / 28;
                int px = (rowbase + r) * IMG_W + (nl - r * 28);
                float v0 = acc[s][j]     + bv0;
                float v1 = acc[s][2 + j] + bv1;
                if (pre) {
                    v0 += pre[(size_t)n * preStride + (size_t)oc0 * HW + px];
                    v1 += pre[(size_t)n * preStride + (size_t)oc1 * HW + px];
                }
                out[(size_t)n * outStride + (size_t)oc0 * HW + px] = v0;
                out[(size_t)n * outStride + (size_t)oc1 * HW + px] = v1;
            }
        }
        return;
    }

    __syncthreads();
#pragma unroll
    for (int s = 0; s < 7; ++s) {
#pragma unroll
        for (int j = 0; j < 2; ++j) {
            int nl = warp_n * 56 + s * 8 + 2 * ctg + j;
            float v0 = acc[s][j]     + bv0;
            float v1 = acc[s][2 + j] + bv1;
            if (pre) {
                int r = nl / 28;
                int px = (rowbase + r) * IMG_W + (nl - r * 28);
                v0 += pre[(size_t)n * preStride + (size_t)oc0 * HW + px];
                v1 += pre[(size_t)n * preStride + (size_t)oc1 * HW + px];
            }
            sm.gates[((m0 >> 3) * 8 + (m0 & 7)) * 112 + nl] = v0;
            sm.gates[((m1 >> 3) * 8 + (m1 & 7)) * 112 + nl] = v1;
        }
    }
    __syncthreads();

#pragma unroll
    for (int k = 0; k < 7; ++k) {
        int e   = tid + k * 128;
        int hcl = e / 112;
        int nl  = e - hcl * 112;
        int r   = nl / 28;
        int px  = (rowbase + r) * IMG_W + (nl - r * 28);
        int hc  = hcb + hcl;

        float g0 = sm.gates[(0 * 8 + hcl) * 112 + nl];
        float g1 = sm.gates[(1 * 8 + hcl) * 112 + nl];
        float g2 = sm.gates[(2 * 8 + hcl) * 112 + nl];
        float g3 = sm.gates[(3 * 8 + hcl) * 112 + nl];

        size_t sidx = ((size_t)n * HC + hc) * HW + px;
        float cv = c[sidx];
        float pi = Wp[(size_t)(0 * HC + hc) * HW + px];
        float pf = Wp[(size_t)(1 * HC + hc) * HW + px];
        float po = Wp[(size_t)(2 * HC + hc) * HW + px];

        float gi = sigmoidf_(g0 + cv * pi);
        float gf = sigmoidf_(g1 + cv * pf);
        float cc = gf * cv + gi * tanhf(g2);
        float go = sigmoidf_(g3 + cc * po);
        float hv = go * tanhf(cc);

        c[sidx] = cc;
        hout[sidx] = hv;
        if (yout)
            yout[(((size_t)n * TSTEPS + t) * HC + hc) * HW + px] = hv;
    }
}

// ---------------- wave kernel: L0(s) | gx0(s+1) | L1(s-1) | L2(s-2) ----------
#define GX0_FRAME ((size_t)4 * HC0 * HW)
#define GX0_BSTR  ((size_t)TSTEPS * 4 * HC0 * HW)

__global__ void __launch_bounds__(128, 4) wave_kernel(
    int s,
    const float* __restrict__ x,
    float* __restrict__ gx0,
    float* __restrict__ state,
    const uint32_t* __restrict__ wt,
    const float* __restrict__ bx0, const float* __restrict__ bx1, const float* __restrict__ bx2,
    const float* __restrict__ Wp0, const float* __restrict__ Wp1, const float* __restrict__ Wp2,
    float* __restrict__ y)
{
    __shared__ SmemU sm;

    float* h0buf[2] = { state + OFF_H0A, state + OFF_H0B };
    float* h1buf[2] = { state + OFF_H1A, state + OFF_H1B };
    float* h2buf[2] = { state + OFF_H2A, state + OFF_H2B };

    const int b = blockIdx.x;

    if (b < 448) {
        // ---- L0 at t = s ----
        const int t = s;
        if (t < 0 || t >= TSTEPS) return;
        int local = b;
        int z = local % 7; local /= 7;
        int yb = local % 8;
        int n  = local / 8;
        const int rb = t & 1, wb = rb ^ 1;
        conv_cell_body(sm, n, yb, z * 4,
                       h0buf[rb], HC0, (size_t)HC0 * HW, nullptr, 0,
                       wt + WOFF_L0, nullptr,
                       gx0 + (size_t)t * GX0_FRAME, GX0_BSTR,
                       HC0, nullptr, 0,
                       Wp0, h0buf[wb], state + OFF_C0, nullptr, t);
    } else if (b < 896) {
        // ---- gx0 at t = s + 1 ----
        const int t = s + 1;
        if (t < 0 || t >= TSTEPS) return;
        int local = b - 448;
        int z = local % 7; local /= 7;
        int yb = local % 8;
        int n  = local / 8;
        conv_cell_body(sm, n, yb, z * 4,
                       x + (size_t)t * CIN0 * HW, CIN0, (size_t)TSTEPS * CIN0 * HW,
                       nullptr, 0,
                       wt + WOFF_GX0, bx0, nullptr, 0,
                       HC0, gx0 + (size_t)t * GX0_FRAME, GX0_BSTR,
                       nullptr, nullptr, nullptr, nullptr, t);
    } else if (b < 1120) {
        // ---- L1 at t = s - 1 ----
        const int t = s - 1;
        if (t < 0 || t >= TSTEPS) return;
        int local = b - 896;
        int z = local % 7; local /= 7;
        int yb = local % 4;
        int n  = local / 4;
        const int rb = t & 1, wb = rb ^ 1;
        conv_cell_body(sm, n, yb, z * 4,
                       h0buf[wb], HC0, (size_t)HC0 * HW,   // h0(t), written at wave s-1
                       h1buf[rb], HC1,
                       wt + WOFF_L1, bx1, nullptr, 0,
                       HC1, nullptr, 0,
                       Wp1, h1buf[wb], state + OFF_C1, nullptr, t);
    } else {
        // ---- L2 at t = s - 2 ----
        const int t = s - 2;
        if (t < 0 || t >= TSTEPS) return;
        int local = b - 1120;
        int z = local % 7; local /= 7;
        int yb = local % 8;
        int n  = local / 8;
        const int rb = t & 1, wb = rb ^ 1;
        conv_cell_body(sm, n, yb, z * 4,
                       h1buf[wb], HC1, (size_t)HC1 * HW,   // h1(t), written at wave s-1
                       h2buf[rb], HC2,
                       wt + WOFF_L2, bx2, nullptr, 0,
                       HC2, nullptr, 0,
                       Wp2, h2buf[wb], state + OFF_C2, y, t);
    }
}

// ---------------- host launch (single stream, no statics) ----------------
extern "C" void kernel_launch(void* const* d_in, const int* in_sizes, int n_in,
                              void* d_out, int out_size)
{
    const float* x   = (const float*)d_in[0];
    const float* Wx0 = (const float*)d_in[1];
    const float* bx0 = (const float*)d_in[2];
    const float* Wh0 = (const float*)d_in[3];
    const float* Wp0 = (const float*)d_in[4];
    const float* Wx1 = (const float*)d_in[5];
    const float* bx1 = (const float*)d_in[6];
    const float* Wh1 = (const float*)d_in[7];
    const float* Wp1 = (const float*)d_in[8];
    const float* Wx2 = (const float*)d_in[9];
    const float* bx2 = (const float*)d_in[10];
    const float* Wh2 = (const float*)d_in[11];
    const float* Wp2 = (const float*)d_in[12];
    float* y = (float*)d_out;

    float *gx0, *state;
    uint32_t* wt;
    cudaGetSymbolAddress((void**)&gx0,   g_gx0);
    cudaGetSymbolAddress((void**)&state, g_state);
    cudaGetSymbolAddress((void**)&wt,    g_wt);

    init_zero_kernel<<<(NSTATE + 255) / 256, 256>>>(state, NSTATE);
    prep_weights<<<(WSZ_GX0 + 255) / 256, 256>>>(Wx0, CIN0, nullptr, 0, HC0, 24, wt + WOFF_GX0, WSZ_GX0);
    prep_weights<<<(WSZ_L0  + 255) / 256, 256>>>(Wh0, HC0,  nullptr, 0, HC0,  8, wt + WOFF_L0,  WSZ_L0);
    prep_weights<<<(WSZ_L1  + 255) / 256, 256>>>(Wx1, HC0,  Wh1, HC1, HC1, 12, wt + WOFF_L1,  WSZ_L1);
    prep_weights<<<(WSZ_L2  + 255) / 256, 256>>>(Wx2, HC1,  Wh2, HC2, HC2, 12, wt + WOFF_L2,  WSZ_L2);

    // waves: s = -1 (gx0(0) only) .. 17 (L2(15) only)
    for (int s = -1; s <= 17; ++s) {
        wave_kernel<<<1568, 128>>>(s, x, gx0, state, wt,
                                   bx0, bx1, bx2, Wp0, Wp1, Wp2, y);
    }
}